// round 7
// baseline (speedup 1.0000x reference)
#include <cuda_runtime.h>
#include <cuda_bf16.h>
#include <cstdint>
#include <math.h>

#define MS      524288
#define NRAYS   8192
#define GXC     160
#define GYC     160
#define GZC     128
#define NFEATC  12
#define TILE_M  256
#define NT2     2048
#define ACT_SHIFT_F (-13.815509557963774f)

// ---------------- device scratch ----------------
__device__ float g_alpha[MS];
__device__ float g_weight[MS];
__device__ float g_wrgb[MS * 3];
__device__ float g_ve[NRAYS * 27];
// swizzled bf16 weight images: 3 layers x [128 n-rows x 256B], XOR-swizzled
__device__ __align__(16) __nv_bfloat16 g_wimg[3 * 16384];

// smem layout (bytes)
#define SM_WT   0
#define SM_ACTA 98304
#define SM_ACTB 163840
#define SM_BIAS 229376
#define SM_WR   230144
#define DYN_SMEM 232064

// ---------------- helpers ----------------
__device__ __forceinline__ uint32_t smem_u32(const void* p) {
    uint32_t a;
    asm("{ .reg .u64 t; cvta.to.shared.u64 t, %1; cvt.u32.u64 %0, t; }" : "=r"(a) : "l"(p));
    return a;
}
__device__ __forceinline__ void ldsm4(uint32_t (&r)[4], uint32_t addr) {
    asm volatile("ldmatrix.sync.aligned.m8n8.x4.shared.b16 {%0,%1,%2,%3}, [%4];"
                 : "=r"(r[0]), "=r"(r[1]), "=r"(r[2]), "=r"(r[3]) : "r"(addr));
}
__device__ __forceinline__ void mma16816(float* c, const uint32_t* a, uint32_t b0, uint32_t b1) {
    asm volatile("mma.sync.aligned.m16n8k16.row.col.f32.bf16.bf16.f32 "
                 "{%0,%1,%2,%3}, {%4,%5,%6,%7}, {%8,%9}, {%0,%1,%2,%3};"
                 : "+f"(c[0]), "+f"(c[1]), "+f"(c[2]), "+f"(c[3])
                 : "r"(a[0]), "r"(a[1]), "r"(a[2]), "r"(a[3]), "r"(b0), "r"(b1));
}
__device__ __forceinline__ uint32_t packbf2(float lo, float hi) {
    uint32_t pk;
    asm("cvt.rn.satfinite.bf16x2.f32 %0, %1, %2;" : "=r"(pk) : "f"(hi), "f"(lo));
    return pk;
}
__device__ __forceinline__ int lb_ray(const int* __restrict__ a, int val) {
    int lo = 0, hi = MS;
    while (lo < hi) {
        int mid = (lo + hi) >> 1;
        if (__ldg(&a[mid]) < val) lo = mid + 1; else hi = mid;
    }
    return lo;
}

// ---------------- kernel 0: swizzled bf16 weight images ----------------
__global__ void k_wprep(const float* __restrict__ W0, const float* __restrict__ W1,
                        const float* __restrict__ W2) {
    int idx = blockIdx.x * 256 + threadIdx.x;
    if (idx >= 3 * 16384) return;
    int l = idx >> 14, r = idx & 16383;
    int n = r >> 7, k = r & 127;        // n = output neuron (B row), k = input
    const float* W = (l == 0) ? W0 : ((l == 1) ? W1 : W2);
    int krows = (l == 0) ? 75 : 128;
    float v = (k < krows) ? __ldg(&W[k * 128 + n]) : 0.f;
    uint32_t sw = ((uint32_t)(k * 2)) ^ (((uint32_t)n & 7) << 4);
    g_wimg[l * 16384 + n * 128 + (sw >> 1)] = __float2bfloat16(v);
}

// ---------------- kernel 1: view posemb ----------------
__global__ void k_ve(const float* __restrict__ viewdirs) {
    int r = blockIdx.x * 256 + threadIdx.x;
    if (r >= NRAYS) return;
    float v0 = viewdirs[3 * r], v1 = viewdirs[3 * r + 1], v2 = viewdirs[3 * r + 2];
    float* row = g_ve + r * 27;
    row[0] = v0; row[1] = v1; row[2] = v2;
#pragma unroll
    for (int d = 0; d < 3; d++) {
        float v = (d == 0) ? v0 : ((d == 1) ? v1 : v2);
        float s, c;
        sincosf(v, &s, &c);
#pragma unroll
        for (int p = 0; p < 4; p++) {
            row[3 + d * 4 + p]  = s;
            row[15 + d * 4 + p] = c;
            float ns = 2.f * s * c;
            float nc = fmaf(c, c, -(s * s));
            s = ns; c = nc;
        }
    }
}

// ---------------- kernel 2: alpha ----------------
__global__ void k_alpha(const float* __restrict__ xyz,
                        const unsigned char* __restrict__ mask,
                        const float* __restrict__ density) {
    int m = blockIdx.x * 256 + threadIdx.x;
    if (m >= MS) return;
    float px = xyz[3 * m], py = xyz[3 * m + 1], pz = xyz[3 * m + 2];

    const float sx = 0.5f * (GXC - 1), sy = 0.5f * (GYC - 1), sz = 0.5f * (GZC - 1);
    int mx = min(max(__float2int_rn(px * sx + sx), 0), GXC - 1);
    int my = min(max(__float2int_rn(py * sy + sy), 0), GYC - 1);
    int mz = min(max(__float2int_rn(pz * sz + sz), 0), GZC - 1);
    bool mk = mask[(mx * GYC + my) * GZC + mz] != 0;

    float tx = fminf(fmaxf((px + 1.f) * sx, 0.f), (float)(GXC - 1));
    float ty = fminf(fmaxf((py + 1.f) * sy, 0.f), (float)(GYC - 1));
    float tz = fminf(fmaxf((pz + 1.f) * sz, 0.f), (float)(GZC - 1));
    int ix = max(min((int)floorf(tx), GXC - 2), 0);
    int iy = max(min((int)floorf(ty), GYC - 2), 0);
    int iz = max(min((int)floorf(tz), GZC - 2), 0);
    float fx = tx - (float)ix, fy = ty - (float)iy, fz = tz - (float)iz;

    float d = 0.f;
#pragma unroll
    for (int dx = 0; dx < 2; dx++)
#pragma unroll
        for (int dy = 0; dy < 2; dy++)
#pragma unroll
            for (int dz = 0; dz < 2; dz++) {
                float w = (dx ? fx : 1.f - fx) * (dy ? fy : 1.f - fy) * (dz ? fz : 1.f - fz);
                float v = __ldg(&density[((ix + dx) * GYC + (iy + dy)) * GZC + (iz + dz)]);
                d = fmaf(w, v, d);
            }

    float e = __expf(d + ACT_SHIFT_F);
    float s = sqrtf(1.f + e);
    float alpha = e / (s * (s + 1.f));
    g_alpha[m] = mk ? alpha : 0.f;
}

// ---------------- kernel 3: warp-per-ray weights + background ----------------
__global__ void k_weights(const int* __restrict__ ray_id, float* __restrict__ out) {
    int r = blockIdx.x * 8 + (threadIdx.x >> 5);
    int lane = threadIdx.x & 31;
    if (r >= NRAYS) return;
    int s = lb_ray(ray_id, r);
    int e = lb_ray(ray_id, r + 1);
    float P = 1.f;
    for (int base = s; base < e; base += 32) {
        int m = base + lane;
        float a = (m < e) ? g_alpha[m] : 0.f;
        float t = fmaxf(1.f - a, 1e-10f);
        float p = t;
#pragma unroll
        for (int off = 1; off < 32; off <<= 1) {
            float o = __shfl_up_sync(0xFFFFFFFFu, p, off);
            if (lane >= off) p *= o;
        }
        float ex = __shfl_up_sync(0xFFFFFFFFu, p, 1);
        if (lane == 0) ex = 1.f;
        if (m < e) g_weight[m] = P * ex * a;
        P *= __shfl_sync(0xFFFFFFFFu, p, 31);
    }
    if (lane == 0) { out[3 * r] = P; out[3 * r + 1] = P; out[3 * r + 2] = P; }
}

// ---------------- kernel 4: persistent HMMA MLP ----------------
template <int KT>
__device__ __forceinline__ void gemm_layer(uint32_t aBase, uint32_t wBase,
                                           uint32_t cbk16, uint32_t swz,
                                           float acc[4][8][4]) {
#pragma unroll
    for (int mt = 0; mt < 4; mt++)
#pragma unroll
        for (int nt = 0; nt < 8; nt++)
#pragma unroll
            for (int j = 0; j < 4; j++) acc[mt][nt][j] = 0.f;
#pragma unroll
    for (int kt = 0; kt < KT; kt++) {
        uint32_t sc = ((uint32_t)(kt * 32) + cbk16) ^ swz;
        uint32_t a[4][4];
#pragma unroll
        for (int mt = 0; mt < 4; mt++) ldsm4(a[mt], aBase + mt * 4096 + sc);
#pragma unroll
        for (int np = 0; np < 4; np++) {
            uint32_t b[4];
            ldsm4(b, wBase + np * 4096 + sc);
#pragma unroll
            for (int mt = 0; mt < 4; mt++) {
                mma16816(acc[mt][2 * np],     a[mt], b[0], b[2]);
                mma16816(acc[mt][2 * np + 1], a[mt], b[1], b[3]);
            }
        }
    }
}

__device__ __forceinline__ void store_act(const float acc[4][8][4], char* out,
                                          const __nv_bfloat16* bias, int r0, int c0, int lane) {
    const int q = lane & 3, rr = lane >> 2;
    const uint32_t swz = (uint32_t)rr << 4;
#pragma unroll
    for (int nt = 0; nt < 8; nt++) {
        int colA = c0 + nt * 8 + q * 2;
        float2 b = __bfloat1622float2(*(const __nv_bfloat162*)(bias + colA));
        uint32_t cb = ((uint32_t)(2 * c0 + nt * 16 + q * 4)) ^ swz;
#pragma unroll
        for (int mt = 0; mt < 4; mt++) {
            int row = r0 + mt * 16 + rr;
            *(uint32_t*)(out + row * 256 + cb) =
                packbf2(fmaxf(acc[mt][nt][0] + b.x, 0.f), fmaxf(acc[mt][nt][1] + b.y, 0.f));
            *(uint32_t*)(out + (row + 8) * 256 + cb) =
                packbf2(fmaxf(acc[mt][nt][2] + b.x, 0.f), fmaxf(acc[mt][nt][3] + b.y, 0.f));
        }
    }
}

__global__ void __launch_bounds__(256, 1) k_mlp(
    const float* __restrict__ xyz, const int* __restrict__ ray_id,
    const float* __restrict__ k0,
    const float* __restrict__ b0, const float* __restrict__ b1,
    const float* __restrict__ b2, const float* __restrict__ Wr,
    const float* __restrict__ br) {
    extern __shared__ char sm[];
    const int tid = threadIdx.x;
    const int lane = tid & 31, warp = tid >> 5;

    // ---- one-time per-CTA setup ----
    {
        const uint4* src = (const uint4*)g_wimg;
        uint4* dst = (uint4*)(sm + SM_WT);
        for (int i = tid; i < 6144; i += 256) dst[i] = src[i];
    }
    __nv_bfloat16* sBias = (__nv_bfloat16*)(sm + SM_BIAS);
    for (int i = tid; i < 384; i += 256) {
        float v = (i < 128) ? __ldg(&b0[i]) : ((i < 256) ? __ldg(&b1[i - 128]) : __ldg(&b2[i - 256]));
        sBias[i] = __float2bfloat16(v);
    }
    float* sWr = (float*)(sm + SM_WR);
    for (int i = tid; i < 465; i += 256) sWr[i] = __ldg(&Wr[i]);
    if (tid < 3) sWr[465 + tid] = __ldg(&br[tid]);
    __syncthreads();

    const uint32_t actA_s = smem_u32(sm + SM_ACTA);
    const uint32_t actB_s = smem_u32(sm + SM_ACTB);
    const uint32_t wt_s   = smem_u32(sm + SM_WT);
    float* sD = (float*)(sm + SM_ACTB);   // overlaid on dead H1 buffer for final partials

    const int r0 = (warp & 3) * 64;       // 4 row groups of 64
    const int cg = warp >> 2;             // 2 col groups
    const int c0 = cg * 64;
    const int rowL = lane & 15, cbk = lane >> 4;
    const uint32_t swzL = ((uint32_t)rowL & 7) << 4;
    const uint32_t cbk16 = (uint32_t)cbk << 4;
    const uint32_t ldA = actA_s + (r0 + rowL) * 256;
    const uint32_t ldB = actB_s + (r0 + rowL) * 256;
    const uint32_t ldW = wt_s + (c0 + rowL) * 256;

    float acc[4][8][4];

    for (int tile = blockIdx.x; tile < NT2; tile += gridDim.x) {
        const int m0 = tile * TILE_M;

        // ---- build X into ACTA (1 thread per row) ----
        {
            const int row = tid;
            const int m = m0 + row;
            const float px = xyz[3 * m], py = xyz[3 * m + 1], pz = xyz[3 * m + 2];
            char* act = sm + SM_ACTA + row * 256;
            const uint32_t swzR = ((uint32_t)row & 7) << 4;
            // trilinear features -> cols 0..11
            float tx = fminf(fmaxf((px + 1.f) * 0.5f * (GXC - 1), 0.f), (float)(GXC - 1));
            float ty = fminf(fmaxf((py + 1.f) * 0.5f * (GYC - 1), 0.f), (float)(GYC - 1));
            float tz = fminf(fmaxf((pz + 1.f) * 0.5f * (GZC - 1), 0.f), (float)(GZC - 1));
            int ix = max(min((int)floorf(tx), GXC - 2), 0);
            int iy = max(min((int)floorf(ty), GYC - 2), 0);
            int iz = max(min((int)floorf(tz), GZC - 2), 0);
            float fx = tx - (float)ix, fy = ty - (float)iy, fz = tz - (float)iz;
            float f[12];
#pragma unroll
            for (int j = 0; j < 12; j++) f[j] = 0.f;
#pragma unroll
            for (int dx = 0; dx < 2; dx++)
#pragma unroll
                for (int dy = 0; dy < 2; dy++)
#pragma unroll
                    for (int dz = 0; dz < 2; dz++) {
                        float w = (dx ? fx : 1.f - fx) * (dy ? fy : 1.f - fy) * (dz ? fz : 1.f - fz);
                        const float4* cp = (const float4*)(k0 +
                            (size_t)(((ix + dx) * GYC + (iy + dy)) * GZC + (iz + dz)) * NFEATC);
                        float4 v0 = __ldg(cp), v1 = __ldg(cp + 1), v2 = __ldg(cp + 2);
                        f[0] = fmaf(w, v0.x, f[0]);  f[1] = fmaf(w, v0.y, f[1]);
                        f[2] = fmaf(w, v0.z, f[2]);  f[3] = fmaf(w, v0.w, f[3]);
                        f[4] = fmaf(w, v1.x, f[4]);  f[5] = fmaf(w, v1.y, f[5]);
                        f[6] = fmaf(w, v1.z, f[6]);  f[7] = fmaf(w, v1.w, f[7]);
                        f[8] = fmaf(w, v2.x, f[8]);  f[9] = fmaf(w, v2.y, f[9]);
                        f[10] = fmaf(w, v2.z, f[10]); f[11] = fmaf(w, v2.w, f[11]);
                    }
#pragma unroll
            for (int j = 0; j < 6; j++)
                *(uint32_t*)(act + (((uint32_t)(j * 4)) ^ swzR)) = packbf2(f[2 * j], f[2 * j + 1]);
            // cols 12..79: xyz, sin, cos, zero pad — staged then word-stored
            float pe[68];
            pe[0] = px; pe[1] = py; pe[2] = pz;
#pragma unroll
            for (int d = 0; d < 3; d++) {
                float v = (d == 0) ? px : ((d == 1) ? py : pz);
                float s, c;
                __sincosf(v, &s, &c);
#pragma unroll
                for (int p = 0; p < 10; p++) {
                    pe[3 + d * 10 + p]  = s;
                    pe[33 + d * 10 + p] = c;
                    float ns = 2.f * s * c;
                    float nc = fmaf(c, c, -(s * s));
                    s = ns; c = nc;
                }
            }
#pragma unroll
            for (int j = 63; j < 68; j++) pe[j] = 0.f;   // cols 75..79
#pragma unroll
            for (int j = 0; j < 34; j++)
                *(uint32_t*)(act + (((uint32_t)(24 + j * 4)) ^ swzR)) =
                    packbf2(pe[2 * j], pe[2 * j + 1]);
        }
        __syncthreads();

        // ---- layer 0: X(A) -> H1(B) ----
        gemm_layer<5>(ldA, ldW, cbk16, swzL, acc);
        store_act(acc, sm + SM_ACTB, sBias, r0, c0, lane);
        __syncthreads();

        // ---- layer 1: H1(B) -> H2(A) ----
        gemm_layer<8>(ldB, ldW + 32768, cbk16, swzL, acc);
        store_act(acc, sm + SM_ACTA, sBias + 128, r0, c0, lane);
        __syncthreads();

        // ---- layer 2: H2(A) -> partial rgb dot (no H3 store) ----
        gemm_layer<8>(ldA, ldW + 65536, cbk16, swzL, acc);
        {
            const int q = lane & 3, rr = lane >> 2;
            const __nv_bfloat16* bias2 = sBias + 256;
            float p[4][2][3];
#pragma unroll
            for (int mt = 0; mt < 4; mt++)
#pragma unroll
                for (int h = 0; h < 2; h++)
#pragma unroll
                    for (int c = 0; c < 3; c++) p[mt][h][c] = 0.f;
#pragma unroll
            for (int nt = 0; nt < 8; nt++) {
                int colA = c0 + nt * 8 + q * 2;
                float2 b = __bfloat1622float2(*(const __nv_bfloat162*)(bias2 + colA));
                float wA0 = sWr[colA * 3], wA1 = sWr[colA * 3 + 1], wA2 = sWr[colA * 3 + 2];
                float wB0 = sWr[colA * 3 + 3], wB1 = sWr[colA * 3 + 4], wB2 = sWr[colA * 3 + 5];
#pragma unroll
                for (int mt = 0; mt < 4; mt++) {
                    float hA = fmaxf(acc[mt][nt][0] + b.x, 0.f);
                    float hB = fmaxf(acc[mt][nt][1] + b.y, 0.f);
                    p[mt][0][0] = fmaf(hA, wA0, fmaf(hB, wB0, p[mt][0][0]));
                    p[mt][0][1] = fmaf(hA, wA1, fmaf(hB, wB1, p[mt][0][1]));
                    p[mt][0][2] = fmaf(hA, wA2, fmaf(hB, wB2, p[mt][0][2]));
                    float hC = fmaxf(acc[mt][nt][2] + b.x, 0.f);
                    float hD = fmaxf(acc[mt][nt][3] + b.y, 0.f);
                    p[mt][1][0] = fmaf(hC, wA0, fmaf(hD, wB0, p[mt][1][0]));
                    p[mt][1][1] = fmaf(hC, wA1, fmaf(hD, wB1, p[mt][1][1]));
                    p[mt][1][2] = fmaf(hC, wA2, fmaf(hD, wB2, p[mt][1][2]));
                }
            }
#pragma unroll
            for (int mt = 0; mt < 4; mt++)
#pragma unroll
                for (int h = 0; h < 2; h++)
#pragma unroll
                    for (int c = 0; c < 3; c++) {
                        float v = p[mt][h][c];
                        v += __shfl_xor_sync(0xFFFFFFFFu, v, 1);
                        v += __shfl_xor_sync(0xFFFFFFFFu, v, 2);
                        p[mt][h][c] = v;
                    }
            if (q == 0) {
#pragma unroll
                for (int mt = 0; mt < 4; mt++)
#pragma unroll
                    for (int h = 0; h < 2; h++) {
                        int row = r0 + mt * 16 + rr + h * 8;
                        float* dp = sD + (cg * 256 + row) * 3;
                        dp[0] = p[mt][h][0]; dp[1] = p[mt][h][1]; dp[2] = p[mt][h][2];
                    }
            }
        }
        __syncthreads();

        // ---- final: add ve part, sigmoid, weight, store ----
        {
            const int row = tid;
            const int m = m0 + row;
            const int rid = __ldg(&ray_id[m]);
            const float wgt = g_weight[m];
            float a0 = sD[row * 3] + sD[(256 + row) * 3] + sWr[465];
            float a1 = sD[row * 3 + 1] + sD[(256 + row) * 3 + 1] + sWr[466];
            float a2 = sD[row * 3 + 2] + sD[(256 + row) * 3 + 2] + sWr[467];
            const float* vp = g_ve + rid * 27;
#pragma unroll
            for (int k = 0; k < 27; k++) {
                float v = __ldg(&vp[k]);
                a0 = fmaf(v, sWr[(128 + k) * 3 + 0], a0);
                a1 = fmaf(v, sWr[(128 + k) * 3 + 1], a1);
                a2 = fmaf(v, sWr[(128 + k) * 3 + 2], a2);
            }
            g_wrgb[3 * m + 0] = wgt * __fdividef(1.f, 1.f + __expf(-a0));
            g_wrgb[3 * m + 1] = wgt * __fdividef(1.f, 1.f + __expf(-a1));
            g_wrgb[3 * m + 2] = wgt * __fdividef(1.f, 1.f + __expf(-a2));
        }
        __syncthreads();
    }
}

// ---------------- kernel 5: warp-per-ray reduction ----------------
__global__ void k_accum(const int* __restrict__ ray_id, float* __restrict__ out) {
    int r = blockIdx.x * 8 + (threadIdx.x >> 5);
    int lane = threadIdx.x & 31;
    if (r >= NRAYS) return;
    int s = lb_ray(ray_id, r);
    int e = lb_ray(ray_id, r + 1);
    float a0 = 0.f, a1 = 0.f, a2 = 0.f;
    for (int m = s + lane; m < e; m += 32) {
        a0 += g_wrgb[3 * m];
        a1 += g_wrgb[3 * m + 1];
        a2 += g_wrgb[3 * m + 2];
    }
#pragma unroll
    for (int off = 16; off > 0; off >>= 1) {
        a0 += __shfl_xor_sync(0xFFFFFFFFu, a0, off);
        a1 += __shfl_xor_sync(0xFFFFFFFFu, a1, off);
        a2 += __shfl_xor_sync(0xFFFFFFFFu, a2, off);
    }
    if (lane == 0) {
        out[3 * r]     += a0;
        out[3 * r + 1] += a1;
        out[3 * r + 2] += a2;
    }
}

// ---------------- launch ----------------
extern "C" void kernel_launch(void* const* d_in, const int* in_sizes, int n_in,
                              void* d_out, int out_size) {
    const float*         xyz      = (const float*)d_in[0];
    const int*           ray_id   = (const int*)d_in[1];
    const float*         viewdirs = (const float*)d_in[2];
    const unsigned char* mask     = (const unsigned char*)d_in[3];
    const float*         density  = (const float*)d_in[4];
    const float*         k0 = (const float*)d_in[5];
    const float*         W0 = (const float*)d_in[6];
    const float*         b0 = (const float*)d_in[7];
    const float*         W1 = (const float*)d_in[8];
    const float*         b1 = (const float*)d_in[9];
    const float*         W2 = (const float*)d_in[10];
    const float*         b2 = (const float*)d_in[11];
    const float*         Wr = (const float*)d_in[12];
    const float*         br = (const float*)d_in[13];
    float* out = (float*)d_out;

    static int smem_set = 0;
    if (!smem_set) {
        cudaFuncSetAttribute(k_mlp, cudaFuncAttributeMaxDynamicSharedMemorySize, DYN_SMEM);
        smem_set = 1;
    }

    k_wprep<<<192, 256>>>(W0, W1, W2);
    k_ve<<<NRAYS / 256, 256>>>(viewdirs);
    k_alpha<<<MS / 256, 256>>>(xyz, mask, density);
    k_weights<<<NRAYS / 8, 256>>>(ray_id, out);
    k_mlp<<<148, 256, DYN_SMEM>>>(xyz, ray_id, k0, b0, b1, b2, Wr, br);
    k_accum<<<NRAYS / 8, 256>>>(ray_id, out);
}

// round 10
// speedup vs baseline: 1.0098x; 1.0098x over previous
#include <cuda_runtime.h>
#include <cuda_bf16.h>
#include <cstdint>
#include <math.h>

#define MS      524288
#define NRAYS   8192
#define GXC     160
#define GYC     160
#define GZC     128
#define NFEATC  12
#define TILE_M  256
#define NT2     2048
#define ACT_SHIFT_F (-13.815509557963774f)

// ---------------- device scratch ----------------
__device__ float g_alpha[MS];
__device__ float g_weight[MS];
__device__ float g_wrgb[MS * 3];
__device__ float g_ve[NRAYS * 27];
// swizzled bf16 weight images: 3 layers x [128 n-rows x 256B], XOR-swizzled
__device__ __align__(16) __nv_bfloat16 g_wimg[3 * 16384];

// smem layout (bytes)
#define SM_WT   0
#define SM_ACTA 98304
#define SM_ACTB 163840
#define SM_BIAS 229376
#define SM_WR   230144
#define DYN_SMEM 232064

// ---------------- helpers ----------------
__device__ __forceinline__ uint32_t smem_u32(const void* p) {
    uint32_t a;
    asm("{ .reg .u64 t; cvta.to.shared.u64 t, %1; cvt.u32.u64 %0, t; }" : "=r"(a) : "l"(p));
    return a;
}
__device__ __forceinline__ void ldsm4(uint32_t (&r)[4], uint32_t addr) {
    asm volatile("ldmatrix.sync.aligned.m8n8.x4.shared.b16 {%0,%1,%2,%3}, [%4];"
                 : "=r"(r[0]), "=r"(r[1]), "=r"(r[2]), "=r"(r[3]) : "r"(addr));
}
__device__ __forceinline__ void mma16816(float* c, const uint32_t* a, uint32_t b0, uint32_t b1) {
    asm volatile("mma.sync.aligned.m16n8k16.row.col.f32.bf16.bf16.f32 "
                 "{%0,%1,%2,%3}, {%4,%5,%6,%7}, {%8,%9}, {%0,%1,%2,%3};"
                 : "+f"(c[0]), "+f"(c[1]), "+f"(c[2]), "+f"(c[3])
                 : "r"(a[0]), "r"(a[1]), "r"(a[2]), "r"(a[3]), "r"(b0), "r"(b1));
}
__device__ __forceinline__ uint32_t packbf2(float lo, float hi) {
    uint32_t pk;
    asm("cvt.rn.satfinite.bf16x2.f32 %0, %1, %2;" : "=r"(pk) : "f"(hi), "f"(lo));
    return pk;
}
__device__ __forceinline__ int lb_ray(const int* __restrict__ a, int val) {
    int lo = 0, hi = MS;
    while (lo < hi) {
        int mid = (lo + hi) >> 1;
        if (__ldg(&a[mid]) < val) lo = mid + 1; else hi = mid;
    }
    return lo;
}

// ---------------- kernel 0: swizzled bf16 weight images ----------------
__global__ void k_wprep(const float* __restrict__ W0, const float* __restrict__ W1,
                        const float* __restrict__ W2) {
    int idx = blockIdx.x * 256 + threadIdx.x;
    if (idx >= 3 * 16384) return;
    int l = idx >> 14, r = idx & 16383;
    int n = r >> 7, k = r & 127;        // n = output neuron (B row), k = input
    const float* W = (l == 0) ? W0 : ((l == 1) ? W1 : W2);
    int krows = (l == 0) ? 75 : 128;
    float v = (k < krows) ? __ldg(&W[k * 128 + n]) : 0.f;
    uint32_t sw = ((uint32_t)(k * 2)) ^ (((uint32_t)n & 7) << 4);
    g_wimg[l * 16384 + n * 128 + (sw >> 1)] = __float2bfloat16(v);
}

// ---------------- kernel 1: view posemb ----------------
__global__ void k_ve(const float* __restrict__ viewdirs) {
    int r = blockIdx.x * 256 + threadIdx.x;
    if (r >= NRAYS) return;
    float v0 = viewdirs[3 * r], v1 = viewdirs[3 * r + 1], v2 = viewdirs[3 * r + 2];
    float* row = g_ve + r * 27;
    row[0] = v0; row[1] = v1; row[2] = v2;
#pragma unroll
    for (int d = 0; d < 3; d++) {
        float v = (d == 0) ? v0 : ((d == 1) ? v1 : v2);
        float s, c;
        sincosf(v, &s, &c);
#pragma unroll
        for (int p = 0; p < 4; p++) {
            row[3 + d * 4 + p]  = s;
            row[15 + d * 4 + p] = c;
            float ns = 2.f * s * c;
            float nc = fmaf(c, c, -(s * s));
            s = ns; c = nc;
        }
    }
}

// ---------------- kernel 2: alpha ----------------
__global__ void k_alpha(const float* __restrict__ xyz,
                        const unsigned char* __restrict__ mask,
                        const float* __restrict__ density) {
    int m = blockIdx.x * 256 + threadIdx.x;
    if (m >= MS) return;
    float px = xyz[3 * m], py = xyz[3 * m + 1], pz = xyz[3 * m + 2];

    const float sx = 0.5f * (GXC - 1), sy = 0.5f * (GYC - 1), sz = 0.5f * (GZC - 1);
    int mx = min(max(__float2int_rn(px * sx + sx), 0), GXC - 1);
    int my = min(max(__float2int_rn(py * sy + sy), 0), GYC - 1);
    int mz = min(max(__float2int_rn(pz * sz + sz), 0), GZC - 1);
    bool mk = mask[(mx * GYC + my) * GZC + mz] != 0;

    float tx = fminf(fmaxf((px + 1.f) * sx, 0.f), (float)(GXC - 1));
    float ty = fminf(fmaxf((py + 1.f) * sy, 0.f), (float)(GYC - 1));
    float tz = fminf(fmaxf((pz + 1.f) * sz, 0.f), (float)(GZC - 1));
    int ix = max(min((int)floorf(tx), GXC - 2), 0);
    int iy = max(min((int)floorf(ty), GYC - 2), 0);
    int iz = max(min((int)floorf(tz), GZC - 2), 0);
    float fx = tx - (float)ix, fy = ty - (float)iy, fz = tz - (float)iz;

    float d = 0.f;
#pragma unroll
    for (int dx = 0; dx < 2; dx++)
#pragma unroll
        for (int dy = 0; dy < 2; dy++)
#pragma unroll
            for (int dz = 0; dz < 2; dz++) {
                float w = (dx ? fx : 1.f - fx) * (dy ? fy : 1.f - fy) * (dz ? fz : 1.f - fz);
                float v = __ldg(&density[((ix + dx) * GYC + (iy + dy)) * GZC + (iz + dz)]);
                d = fmaf(w, v, d);
            }

    float e = __expf(d + ACT_SHIFT_F);
    float s = sqrtf(1.f + e);
    float alpha = e / (s * (s + 1.f));
    g_alpha[m] = mk ? alpha : 0.f;
}

// ---------------- kernel 3: warp-per-ray weights + background ----------------
__global__ void k_weights(const int* __restrict__ ray_id, float* __restrict__ out) {
    int r = blockIdx.x * 8 + (threadIdx.x >> 5);
    int lane = threadIdx.x & 31;
    if (r >= NRAYS) return;
    int s = lb_ray(ray_id, r);
    int e = lb_ray(ray_id, r + 1);
    float P = 1.f;
    for (int base = s; base < e; base += 32) {
        int m = base + lane;
        float a = (m < e) ? g_alpha[m] : 0.f;
        float t = fmaxf(1.f - a, 1e-10f);
        float p = t;
#pragma unroll
        for (int off = 1; off < 32; off <<= 1) {
            float o = __shfl_up_sync(0xFFFFFFFFu, p, off);
            if (lane >= off) p *= o;
        }
        float ex = __shfl_up_sync(0xFFFFFFFFu, p, 1);
        if (lane == 0) ex = 1.f;
        if (m < e) g_weight[m] = P * ex * a;
        P *= __shfl_sync(0xFFFFFFFFu, p, 31);
    }
    if (lane == 0) { out[3 * r] = P; out[3 * r + 1] = P; out[3 * r + 2] = P; }
}

// ---------------- kernel 4: persistent HMMA MLP (16 warps, TILE_M=256) -------
template <int KT>
__device__ __forceinline__ void gemm_layer(uint32_t aBase, uint32_t wBase,
                                           uint32_t cbk16, uint32_t swz,
                                           float acc[2][8][4]) {
#pragma unroll
    for (int mt = 0; mt < 2; mt++)
#pragma unroll
        for (int nt = 0; nt < 8; nt++)
#pragma unroll
            for (int j = 0; j < 4; j++) acc[mt][nt][j] = 0.f;
#pragma unroll
    for (int kt = 0; kt < KT; kt++) {
        uint32_t sc = ((uint32_t)(kt * 32) + cbk16) ^ swz;
        uint32_t a[2][4];
        ldsm4(a[0], aBase + sc);
        ldsm4(a[1], aBase + 4096 + sc);
#pragma unroll
        for (int np = 0; np < 4; np++) {
            uint32_t b[4];
            ldsm4(b, wBase + np * 4096 + sc);
#pragma unroll
            for (int mt = 0; mt < 2; mt++) {
                mma16816(acc[mt][2 * np],     a[mt], b[0], b[2]);
                mma16816(acc[mt][2 * np + 1], a[mt], b[1], b[3]);
            }
        }
    }
}

__device__ __forceinline__ void store_act(const float acc[2][8][4], char* out,
                                          const __nv_bfloat16* bias, int r0, int c0, int lane) {
    const int q = lane & 3, rr = lane >> 2;
    const uint32_t swz = (uint32_t)rr << 4;
#pragma unroll
    for (int nt = 0; nt < 8; nt++) {
        int colA = c0 + nt * 8 + q * 2;
        float2 b = __bfloat1622float2(*(const __nv_bfloat162*)(bias + colA));
        uint32_t cb = ((uint32_t)(2 * c0 + nt * 16 + q * 4)) ^ swz;
#pragma unroll
        for (int mt = 0; mt < 2; mt++) {
            int row = r0 + mt * 16 + rr;
            *(uint32_t*)(out + row * 256 + cb) =
                packbf2(fmaxf(acc[mt][nt][0] + b.x, 0.f), fmaxf(acc[mt][nt][1] + b.y, 0.f));
            *(uint32_t*)(out + (row + 8) * 256 + cb) =
                packbf2(fmaxf(acc[mt][nt][2] + b.x, 0.f), fmaxf(acc[mt][nt][3] + b.y, 0.f));
        }
    }
}

__global__ void __launch_bounds__(512, 1) k_mlp(
    const float* __restrict__ xyz, const int* __restrict__ ray_id,
    const float* __restrict__ k0,
    const float* __restrict__ b0, const float* __restrict__ b1,
    const float* __restrict__ b2, const float* __restrict__ Wr,
    const float* __restrict__ br) {
    extern __shared__ char sm[];
    const int tid = threadIdx.x;
    const int lane = tid & 31, warp = tid >> 5;

    // ---- one-time per-CTA setup ----
    {
        const uint4* src = (const uint4*)g_wimg;
        uint4* dst = (uint4*)(sm + SM_WT);
        for (int i = tid; i < 6144; i += 512) dst[i] = src[i];
    }
    __nv_bfloat16* sBias = (__nv_bfloat16*)(sm + SM_BIAS);
    if (tid < 384) {
        int i = tid;
        float v = (i < 128) ? __ldg(&b0[i]) : ((i < 256) ? __ldg(&b1[i - 128]) : __ldg(&b2[i - 256]));
        sBias[i] = __float2bfloat16(v);
    }
    float* sWr = (float*)(sm + SM_WR);
    if (tid < 465) sWr[tid] = __ldg(&Wr[tid]);
    if (tid >= 505 && tid < 508) sWr[465 + tid - 505] = __ldg(&br[tid - 505]);
    __syncthreads();

    const uint32_t actA_s = smem_u32(sm + SM_ACTA);
    const uint32_t actB_s = smem_u32(sm + SM_ACTB);
    const uint32_t wt_s   = smem_u32(sm + SM_WT);

    const int r0 = (warp & 7) * 32;       // 8 row groups of 32
    const int c0 = (warp >> 3) * 64;      // 2 col groups of 64
    const int rowL = lane & 15, cbk = lane >> 4;
    const uint32_t swzL = ((uint32_t)rowL & 7) << 4;
    const uint32_t cbk16 = (uint32_t)cbk << 4;
    const uint32_t ldA = actA_s + (r0 + rowL) * 256;
    const uint32_t ldB = actB_s + (r0 + rowL) * 256;
    const uint32_t ldW = wt_s + (c0 + rowL) * 256;

    float acc[2][8][4];

    for (int tile = blockIdx.x; tile < NT2; tile += gridDim.x) {
        const int m0 = tile * TILE_M;

        // ---- build X into ACTA (2 threads per row) ----
        {
            const int row = tid >> 1;
            const int m = m0 + row;
            const float px = xyz[3 * m], py = xyz[3 * m + 1], pz = xyz[3 * m + 2];
            char* act = sm + SM_ACTA + row * 256;
            const uint32_t swzR = ((uint32_t)row & 7) << 4;
            if ((tid & 1) == 0) {
                // trilinear features -> cols 0..11, zero cols 76..79
                float tx = fminf(fmaxf((px + 1.f) * 0.5f * (GXC - 1), 0.f), (float)(GXC - 1));
                float ty = fminf(fmaxf((py + 1.f) * 0.5f * (GYC - 1), 0.f), (float)(GYC - 1));
                float tz = fminf(fmaxf((pz + 1.f) * 0.5f * (GZC - 1), 0.f), (float)(GZC - 1));
                int ix = max(min((int)floorf(tx), GXC - 2), 0);
                int iy = max(min((int)floorf(ty), GYC - 2), 0);
                int iz = max(min((int)floorf(tz), GZC - 2), 0);
                float fx = tx - (float)ix, fy = ty - (float)iy, fz = tz - (float)iz;
                float f[12];
#pragma unroll
                for (int j = 0; j < 12; j++) f[j] = 0.f;
#pragma unroll
                for (int dx = 0; dx < 2; dx++)
#pragma unroll
                    for (int dy = 0; dy < 2; dy++)
#pragma unroll
                        for (int dz = 0; dz < 2; dz++) {
                            float w = (dx ? fx : 1.f - fx) * (dy ? fy : 1.f - fy) * (dz ? fz : 1.f - fz);
                            const float4* cp = (const float4*)(k0 +
                                (size_t)(((ix + dx) * GYC + (iy + dy)) * GZC + (iz + dz)) * NFEATC);
                            float4 v0 = __ldg(cp), v1 = __ldg(cp + 1), v2 = __ldg(cp + 2);
                            f[0] = fmaf(w, v0.x, f[0]);  f[1] = fmaf(w, v0.y, f[1]);
                            f[2] = fmaf(w, v0.z, f[2]);  f[3] = fmaf(w, v0.w, f[3]);
                            f[4] = fmaf(w, v1.x, f[4]);  f[5] = fmaf(w, v1.y, f[5]);
                            f[6] = fmaf(w, v1.z, f[6]);  f[7] = fmaf(w, v1.w, f[7]);
                            f[8] = fmaf(w, v2.x, f[8]);  f[9] = fmaf(w, v2.y, f[9]);
                            f[10] = fmaf(w, v2.z, f[10]); f[11] = fmaf(w, v2.w, f[11]);
                        }
#pragma unroll
                for (int j = 0; j < 6; j++)
                    *(uint32_t*)(act + (((uint32_t)(j * 4)) ^ swzR)) = packbf2(f[2 * j], f[2 * j + 1]);
                *(uint32_t*)(act + (152u ^ swzR)) = 0;   // cols 76,77
                *(uint32_t*)(act + (156u ^ swzR)) = 0;   // cols 78,79
            } else {
                // posemb -> cols 12..75 (col 75 zero)
                float pe[64];
                pe[0] = px; pe[1] = py; pe[2] = pz;
#pragma unroll
                for (int d = 0; d < 3; d++) {
                    float v = (d == 0) ? px : ((d == 1) ? py : pz);
                    float s, c;
                    __sincosf(v, &s, &c);
#pragma unroll
                    for (int p = 0; p < 10; p++) {
                        pe[3 + d * 10 + p]  = s;
                        pe[33 + d * 10 + p] = c;
                        float ns = 2.f * s * c;
                        float nc = fmaf(c, c, -(s * s));
                        s = ns; c = nc;
                    }
                }
                pe[63] = 0.f;
#pragma unroll
                for (int j = 0; j < 32; j++)
                    *(uint32_t*)(act + (((uint32_t)(24 + j * 4)) ^ swzR)) =
                        packbf2(pe[2 * j], pe[2 * j + 1]);
            }
        }
        __syncthreads();

        // ---- layer 0: X(A) -> H1(B) ----
        gemm_layer<5>(ldA, ldW, cbk16, swzL, acc);
        store_act(acc, sm + SM_ACTB, sBias, r0, c0, lane);
        __syncthreads();

        // ---- layer 1: H1(B) -> H2(A) ----
        gemm_layer<8>(ldB, ldW + 32768, cbk16, swzL, acc);
        store_act(acc, sm + SM_ACTA, sBias + 128, r0, c0, lane);
        __syncthreads();

        // ---- layer 2: H2(A) -> H3(B) ----
        gemm_layer<8>(ldA, ldW + 65536, cbk16, swzL, acc);
        store_act(acc, sm + SM_ACTB, sBias + 256, r0, c0, lane);
        __syncthreads();

        // ---- final: rgb = sigmoid([H3 | ve] @ Wr + br), write weight*rgb ----
        {
            const int row = tid >> 1, half = tid & 1;
            const int m = m0 + row;
            const uint32_t swzR = ((uint32_t)row & 7) << 4;
            const char* hrow = sm + SM_ACTB + row * 256;
            float d0 = 0.f, d1 = 0.f, d2 = 0.f;
#pragma unroll
            for (int c = 0; c < 8; c++) {
                uint4 ch = *(const uint4*)(hrow + (((uint32_t)(half * 128 + c * 16)) ^ swzR));
                const uint32_t w[4] = {ch.x, ch.y, ch.z, ch.w};
#pragma unroll
                for (int j = 0; j < 4; j++) {
                    float2 hv = __bfloat1622float2(*(const __nv_bfloat162*)&w[j]);
                    int col = half * 64 + c * 8 + 2 * j;
                    d0 = fmaf(hv.x, sWr[col * 3 + 0], fmaf(hv.y, sWr[(col + 1) * 3 + 0], d0));
                    d1 = fmaf(hv.x, sWr[col * 3 + 1], fmaf(hv.y, sWr[(col + 1) * 3 + 1], d1));
                    d2 = fmaf(hv.x, sWr[col * 3 + 2], fmaf(hv.y, sWr[(col + 1) * 3 + 2], d2));
                }
            }
            d0 += __shfl_xor_sync(0xFFFFFFFFu, d0, 1);
            d1 += __shfl_xor_sync(0xFFFFFFFFu, d1, 1);
            d2 += __shfl_xor_sync(0xFFFFFFFFu, d2, 1);
            if (half == 0) {
                const int rid = __ldg(&ray_id[m]);
                const float wgt = g_weight[m];
                const float* vp = g_ve + rid * 27;
                float a0 = sWr[465] + d0, a1 = sWr[466] + d1, a2 = sWr[467] + d2;
#pragma unroll
                for (int k = 0; k < 27; k++) {
                    float v = __ldg(&vp[k]);
                    a0 = fmaf(v, sWr[(128 + k) * 3 + 0], a0);
                    a1 = fmaf(v, sWr[(128 + k) * 3 + 1], a1);
                    a2 = fmaf(v, sWr[(128 + k) * 3 + 2], a2);
                }
                g_wrgb[3 * m + 0] = wgt * __fdividef(1.f, 1.f + __expf(-a0));
                g_wrgb[3 * m + 1] = wgt * __fdividef(1.f, 1.f + __expf(-a1));
                g_wrgb[3 * m + 2] = wgt * __fdividef(1.f, 1.f + __expf(-a2));
            }
        }
        __syncthreads();
    }
}

// ---------------- kernel 5: warp-per-ray reduction ----------------
__global__ void k_accum(const int* __restrict__ ray_id, float* __restrict__ out) {
    int r = blockIdx.x * 8 + (threadIdx.x >> 5);
    int lane = threadIdx.x & 31;
    if (r >= NRAYS) return;
    int s = lb_ray(ray_id, r);
    int e = lb_ray(ray_id, r + 1);
    float a0 = 0.f, a1 = 0.f, a2 = 0.f;
    for (int m = s + lane; m < e; m += 32) {
        a0 += g_wrgb[3 * m];
        a1 += g_wrgb[3 * m + 1];
        a2 += g_wrgb[3 * m + 2];
    }
#pragma unroll
    for (int off = 16; off > 0; off >>= 1) {
        a0 += __shfl_xor_sync(0xFFFFFFFFu, a0, off);
        a1 += __shfl_xor_sync(0xFFFFFFFFu, a1, off);
        a2 += __shfl_xor_sync(0xFFFFFFFFu, a2, off);
    }
    if (lane == 0) {
        out[3 * r]     += a0;
        out[3 * r + 1] += a1;
        out[3 * r + 2] += a2;
    }
}

// ---------------- launch ----------------
extern "C" void kernel_launch(void* const* d_in, const int* in_sizes, int n_in,
                              void* d_out, int out_size) {
    const float*         xyz      = (const float*)d_in[0];
    const int*           ray_id   = (const int*)d_in[1];
    const float*         viewdirs = (const float*)d_in[2];
    const unsigned char* mask     = (const unsigned char*)d_in[3];
    const float*         density  = (const float*)d_in[4];
    const float*         k0 = (const float*)d_in[5];
    const float*         W0 = (const float*)d_in[6];
    const float*         b0 = (const float*)d_in[7];
    const float*         W1 = (const float*)d_in[8];
    const float*         b1 = (const float*)d_in[9];
    const float*         W2 = (const float*)d_in[10];
    const float*         b2 = (const float*)d_in[11];
    const float*         Wr = (const float*)d_in[12];
    const float*         br = (const float*)d_in[13];
    float* out = (float*)d_out;

    static int smem_set = 0;
    if (!smem_set) {
        cudaFuncSetAttribute(k_mlp, cudaFuncAttributeMaxDynamicSharedMemorySize, DYN_SMEM);
        smem_set = 1;
    }

    k_wprep<<<192, 256>>>(W0, W1, W2);
    k_ve<<<NRAYS / 256, 256>>>(viewdirs);
    k_alpha<<<MS / 256, 256>>>(xyz, mask, density);
    k_weights<<<NRAYS / 8, 256>>>(ray_id, out);
    k_mlp<<<148, 512, DYN_SMEM>>>(xyz, ray_id, k0, b0, b1, b2, Wr, br);
    k_accum<<<NRAYS / 8, 256>>>(ray_id, out);
}

// round 11
// speedup vs baseline: 1.2746x; 1.2623x over previous
#include <cuda_runtime.h>
#include <cuda_bf16.h>
#include <cstdint>
#include <math.h>

#define MS      524288
#define NRAYS   8192
#define GXC     160
#define GYC     160
#define GZC     128
#define NFEATC  12
#define NTILES  4096
#define ACT_SHIFT_F (-13.815509557963774f)

// padded row stride for bf16 tiles: 136 elems = 272 bytes (272/4 mod 32 = 4 -> conflict-free)
#define RSTRIDE 272

// ---------------- device scratch ----------------
__device__ float g_alpha[MS];
__device__ float g_weight[MS];
__device__ float g_wrgb[MS * 3];
__device__ float g_ve[NRAYS * 27];
__device__ __align__(16) __nv_bfloat16 g_wimg[3 * 128 * 136];   // Wt[n][k], padded

// smem layout (bytes)
#define SM_WT   0
#define SM_ACTA 104448
#define SM_ACTB 139264
#define SM_BIAS 174080
#define SM_WR   175616
#define DYN_SMEM 177536

// ---------------- helpers ----------------
__device__ __forceinline__ uint32_t smem_u32(const void* p) {
    uint32_t a;
    asm("{ .reg .u64 t; cvta.to.shared.u64 t, %1; cvt.u32.u64 %0, t; }" : "=r"(a) : "l"(p));
    return a;
}
__device__ __forceinline__ void ldsm4(uint32_t* r, uint32_t addr) {
    asm volatile("ldmatrix.sync.aligned.m8n8.x4.shared.b16 {%0,%1,%2,%3}, [%4];"
                 : "=r"(r[0]), "=r"(r[1]), "=r"(r[2]), "=r"(r[3]) : "r"(addr));
}
__device__ __forceinline__ void mma16816(float* c, const uint32_t* a, uint32_t b0, uint32_t b1) {
    asm volatile("mma.sync.aligned.m16n8k16.row.col.f32.bf16.bf16.f32 "
                 "{%0,%1,%2,%3}, {%4,%5,%6,%7}, {%8,%9}, {%0,%1,%2,%3};"
                 : "+f"(c[0]), "+f"(c[1]), "+f"(c[2]), "+f"(c[3])
                 : "r"(a[0]), "r"(a[1]), "r"(a[2]), "r"(a[3]), "r"(b0), "r"(b1));
}
__device__ __forceinline__ uint32_t packbf2(float lo, float hi) {
    uint32_t pk;
    asm("cvt.rn.satfinite.bf16x2.f32 %0, %1, %2;" : "=r"(pk) : "f"(hi), "f"(lo));
    return pk;
}
__device__ __forceinline__ int lb_ray(const int* __restrict__ a, int val) {
    int lo = 0, hi = MS;
    while (lo < hi) {
        int mid = (lo + hi) >> 1;
        if (__ldg(&a[mid]) < val) lo = mid + 1; else hi = mid;
    }
    return lo;
}

// ---------------- kernel 0: transpose weights to bf16 Wt[n][k] ----------------
__global__ void k_wprep(const float* __restrict__ W0, const float* __restrict__ W1,
                        const float* __restrict__ W2) {
    int idx = blockIdx.x * 256 + threadIdx.x;
    if (idx >= 3 * 128 * 136) return;
    int l = idx / (128 * 136);
    int r = idx % (128 * 136);
    int n = r / 136, k = r % 136;
    const float* W = (l == 0) ? W0 : ((l == 1) ? W1 : W2);
    int krows = (l == 0) ? 75 : 128;
    float v = (k < krows) ? __ldg(&W[k * 128 + n]) : 0.f;
    g_wimg[idx] = __float2bfloat16(v);
}

// ---------------- kernel 1: view posemb ----------------
__global__ void k_ve(const float* __restrict__ viewdirs) {
    int r = blockIdx.x * 256 + threadIdx.x;
    if (r >= NRAYS) return;
    float v0 = viewdirs[3 * r], v1 = viewdirs[3 * r + 1], v2 = viewdirs[3 * r + 2];
    float* row = g_ve + r * 27;
    row[0] = v0; row[1] = v1; row[2] = v2;
#pragma unroll
    for (int d = 0; d < 3; d++) {
        float v = (d == 0) ? v0 : ((d == 1) ? v1 : v2);
        float s, c;
        sincosf(v, &s, &c);
#pragma unroll
        for (int p = 0; p < 4; p++) {
            row[3 + d * 4 + p]  = s;
            row[15 + d * 4 + p] = c;
            float ns = 2.f * s * c;
            float nc = fmaf(c, c, -(s * s));
            s = ns; c = nc;
        }
    }
}

// ---------------- kernel 2: alpha ----------------
__global__ void k_alpha(const float* __restrict__ xyz,
                        const unsigned char* __restrict__ mask,
                        const float* __restrict__ density) {
    int m = blockIdx.x * 256 + threadIdx.x;
    if (m >= MS) return;
    float px = xyz[3 * m], py = xyz[3 * m + 1], pz = xyz[3 * m + 2];

    const float sx = 0.5f * (GXC - 1), sy = 0.5f * (GYC - 1), sz = 0.5f * (GZC - 1);
    int mx = min(max(__float2int_rn(px * sx + sx), 0), GXC - 1);
    int my = min(max(__float2int_rn(py * sy + sy), 0), GYC - 1);
    int mz = min(max(__float2int_rn(pz * sz + sz), 0), GZC - 1);
    bool mk = mask[(mx * GYC + my) * GZC + mz] != 0;

    float tx = fminf(fmaxf((px + 1.f) * sx, 0.f), (float)(GXC - 1));
    float ty = fminf(fmaxf((py + 1.f) * sy, 0.f), (float)(GYC - 1));
    float tz = fminf(fmaxf((pz + 1.f) * sz, 0.f), (float)(GZC - 1));
    int ix = max(min((int)floorf(tx), GXC - 2), 0);
    int iy = max(min((int)floorf(ty), GYC - 2), 0);
    int iz = max(min((int)floorf(tz), GZC - 2), 0);
    float fx = tx - (float)ix, fy = ty - (float)iy, fz = tz - (float)iz;

    float d = 0.f;
#pragma unroll
    for (int dx = 0; dx < 2; dx++)
#pragma unroll
        for (int dy = 0; dy < 2; dy++)
#pragma unroll
            for (int dz = 0; dz < 2; dz++) {
                float w = (dx ? fx : 1.f - fx) * (dy ? fy : 1.f - fy) * (dz ? fz : 1.f - fz);
                float v = __ldg(&density[((ix + dx) * GYC + (iy + dy)) * GZC + (iz + dz)]);
                d = fmaf(w, v, d);
            }

    float e = __expf(d + ACT_SHIFT_F);
    float s = sqrtf(1.f + e);
    float alpha = e / (s * (s + 1.f));
    g_alpha[m] = mk ? alpha : 0.f;
}

// ---------------- kernel 3: warp-per-ray weights + background ----------------
__global__ void k_weights(const int* __restrict__ ray_id, float* __restrict__ out) {
    int r = blockIdx.x * 8 + (threadIdx.x >> 5);
    int lane = threadIdx.x & 31;
    if (r >= NRAYS) return;
    int s = lb_ray(ray_id, r);
    int e = lb_ray(ray_id, r + 1);
    float P = 1.f;
    for (int base = s; base < e; base += 32) {
        int m = base + lane;
        float a = (m < e) ? g_alpha[m] : 0.f;
        float t = fmaxf(1.f - a, 1e-10f);
        float p = t;
#pragma unroll
        for (int off = 1; off < 32; off <<= 1) {
            float o = __shfl_up_sync(0xFFFFFFFFu, p, off);
            if (lane >= off) p *= o;
        }
        float ex = __shfl_up_sync(0xFFFFFFFFu, p, 1);
        if (lane == 0) ex = 1.f;
        if (m < e) g_weight[m] = P * ex * a;
        P *= __shfl_sync(0xFFFFFFFFu, p, 31);
    }
    if (lane == 0) { out[3 * r] = P; out[3 * r + 1] = P; out[3 * r + 2] = P; }
}

// ---------------- kernel 4: persistent HMMA MLP (pipelined frags) ------------
template <int KT>
__device__ __forceinline__ void gemm_layer(uint32_t aoff, uint32_t woff, float acc[2][8][4]) {
#pragma unroll
    for (int mt = 0; mt < 2; mt++)
#pragma unroll
        for (int nt = 0; nt < 8; nt++)
#pragma unroll
            for (int j = 0; j < 4; j++) acc[mt][nt][j] = 0.f;

    uint32_t a[2][2][4];   // [buf][mt][frag]
    uint32_t b[2][4][4];   // [buf][np][frag]

    // prologue: load kt=0 fragments
    ldsm4(a[0][0], aoff);
    ldsm4(a[0][1], aoff + 16 * RSTRIDE);
#pragma unroll
    for (int np = 0; np < 4; np++) ldsm4(b[0][np], woff + np * 16 * RSTRIDE);

#pragma unroll
    for (int kt = 0; kt < KT; kt++) {
        const int cur = kt & 1, nxt = cur ^ 1;
        if (kt + 1 < KT) {
            ldsm4(a[nxt][0], aoff + (kt + 1) * 32);
            ldsm4(a[nxt][1], aoff + 16 * RSTRIDE + (kt + 1) * 32);
#pragma unroll
            for (int np = 0; np < 4; np++)
                ldsm4(b[nxt][np], woff + np * 16 * RSTRIDE + (kt + 1) * 32);
        }
#pragma unroll
        for (int np = 0; np < 4; np++) {
#pragma unroll
            for (int mt = 0; mt < 2; mt++) {
                mma16816(acc[mt][2 * np],     a[cur][mt], b[cur][np][0], b[cur][np][2]);
                mma16816(acc[mt][2 * np + 1], a[cur][mt], b[cur][np][1], b[cur][np][3]);
            }
        }
    }
}

__device__ __forceinline__ void store_act(const float acc[2][8][4], char* actOut,
                                          const float* bias, int r0, int c0, int lane) {
    const float2* bv = (const float2*)bias;
    int q = lane & 3, rr = lane >> 2;
#pragma unroll
    for (int nt = 0; nt < 8; nt++) {
        int col = c0 + nt * 8 + q * 2;
        float2 b = bv[col >> 1];
#pragma unroll
        for (int mt = 0; mt < 2; mt++) {
            float h0 = fmaxf(acc[mt][nt][0] + b.x, 0.f);
            float h1 = fmaxf(acc[mt][nt][1] + b.y, 0.f);
            float h2 = fmaxf(acc[mt][nt][2] + b.x, 0.f);
            float h3 = fmaxf(acc[mt][nt][3] + b.y, 0.f);
            int row0 = r0 + mt * 16 + rr;
            *(uint32_t*)(actOut + row0 * RSTRIDE + col * 2)       = packbf2(h0, h1);
            *(uint32_t*)(actOut + (row0 + 8) * RSTRIDE + col * 2) = packbf2(h2, h3);
        }
    }
}

__global__ void __launch_bounds__(256, 1) k_mlp(
    const float* __restrict__ xyz, const int* __restrict__ ray_id,
    const float* __restrict__ k0,
    const float* __restrict__ b0, const float* __restrict__ b1,
    const float* __restrict__ b2, const float* __restrict__ Wr,
    const float* __restrict__ br) {
    extern __shared__ char sm[];
    const int tid = threadIdx.x;
    const int lane = tid & 31, warp = tid >> 5;

    // ---- one-time per-CTA setup ----
    {
        const uint4* src = (const uint4*)g_wimg;
        uint4* dst = (uint4*)(sm + SM_WT);
        for (int i = tid; i < 6528; i += 256) dst[i] = src[i];
        uint4 z = make_uint4(0, 0, 0, 0);
        uint4* pA = (uint4*)(sm + SM_ACTA);
        for (int i = tid; i < 2176; i += 256) pA[i] = z;
    }
    float* sBias = (float*)(sm + SM_BIAS);
    for (int i = tid; i < 384; i += 256)
        sBias[i] = (i < 128) ? __ldg(&b0[i]) : ((i < 256) ? __ldg(&b1[i - 128]) : __ldg(&b2[i - 256]));
    float* sWr = (float*)(sm + SM_WR);
    for (int i = tid; i < 465; i += 256) sWr[i] = __ldg(&Wr[i]);
    __syncthreads();

    const uint32_t actA_s = smem_u32(sm + SM_ACTA);
    const uint32_t actB_s = smem_u32(sm + SM_ACTB);
    const uint32_t wt_s   = smem_u32(sm + SM_WT);
    const int r0 = (warp & 3) * 32;
    const int c0 = (warp >> 2) * 64;
    const int rowL = lane & 15, cbk = lane >> 4;
    const uint32_t ldA = actA_s + (r0 + rowL) * RSTRIDE + cbk * 16;
    const uint32_t ldB = actB_s + (r0 + rowL) * RSTRIDE + cbk * 16;
    const uint32_t ldW = wt_s + (c0 + rowL) * RSTRIDE + cbk * 16;
    const float br0 = __ldg(&br[0]), br1 = __ldg(&br[1]), br2 = __ldg(&br[2]);

    float acc[2][8][4];

    for (int tile = blockIdx.x; tile < NTILES; tile += gridDim.x) {
        const int m0 = tile * 128;

        // ---- build X into actA (2 threads per row) ----
        // (no barrier needed before this: build writes ACTA only; the preceding
        //  final phase reads ACTB only, and gemm0's ACTB stores come after the
        //  post-build __syncthreads below.)
        {
            const int row = tid >> 1;
            const int m = m0 + row;
            const float px = xyz[3 * m], py = xyz[3 * m + 1], pz = xyz[3 * m + 2];
            char* act = sm + SM_ACTA + row * RSTRIDE;
            if ((tid & 1) == 0) {
                float tx = fminf(fmaxf((px + 1.f) * 0.5f * (GXC - 1), 0.f), (float)(GXC - 1));
                float ty = fminf(fmaxf((py + 1.f) * 0.5f * (GYC - 1), 0.f), (float)(GYC - 1));
                float tz = fminf(fmaxf((pz + 1.f) * 0.5f * (GZC - 1), 0.f), (float)(GZC - 1));
                int ix = max(min((int)floorf(tx), GXC - 2), 0);
                int iy = max(min((int)floorf(ty), GYC - 2), 0);
                int iz = max(min((int)floorf(tz), GZC - 2), 0);
                float fx = tx - (float)ix, fy = ty - (float)iy, fz = tz - (float)iz;
                float f[12];
#pragma unroll
                for (int j = 0; j < 12; j++) f[j] = 0.f;
#pragma unroll
                for (int dx = 0; dx < 2; dx++)
#pragma unroll
                    for (int dy = 0; dy < 2; dy++)
#pragma unroll
                        for (int dz = 0; dz < 2; dz++) {
                            float w = (dx ? fx : 1.f - fx) * (dy ? fy : 1.f - fy) * (dz ? fz : 1.f - fz);
                            const float4* cp = (const float4*)(k0 +
                                (size_t)(((ix + dx) * GYC + (iy + dy)) * GZC + (iz + dz)) * NFEATC);
                            float4 v0 = __ldg(cp), v1 = __ldg(cp + 1), v2 = __ldg(cp + 2);
                            f[0] = fmaf(w, v0.x, f[0]);  f[1] = fmaf(w, v0.y, f[1]);
                            f[2] = fmaf(w, v0.z, f[2]);  f[3] = fmaf(w, v0.w, f[3]);
                            f[4] = fmaf(w, v1.x, f[4]);  f[5] = fmaf(w, v1.y, f[5]);
                            f[6] = fmaf(w, v1.z, f[6]);  f[7] = fmaf(w, v1.w, f[7]);
                            f[8] = fmaf(w, v2.x, f[8]);  f[9] = fmaf(w, v2.y, f[9]);
                            f[10] = fmaf(w, v2.z, f[10]); f[11] = fmaf(w, v2.w, f[11]);
                        }
#pragma unroll
                for (int j = 0; j < 6; j++)
                    *(uint32_t*)(act + j * 4) = packbf2(f[2 * j], f[2 * j + 1]);
                *(uint16_t*)(act + 150) = 0;          // col 75
                *(uint32_t*)(act + 152) = 0;          // cols 76,77
                *(uint32_t*)(act + 156) = 0;          // cols 78,79
            } else {
                *(__nv_bfloat16*)(act + 24) = __float2bfloat16(px);
                *(__nv_bfloat16*)(act + 26) = __float2bfloat16(py);
                *(__nv_bfloat16*)(act + 28) = __float2bfloat16(pz);
#pragma unroll
                for (int d = 0; d < 3; d++) {
                    float v = (d == 0) ? px : ((d == 1) ? py : pz);
                    float s, c;
                    __sincosf(v, &s, &c);
#pragma unroll
                    for (int p = 0; p < 10; p++) {
                        *(__nv_bfloat16*)(act + (15 + d * 10 + p) * 2) = __float2bfloat16(s);
                        *(__nv_bfloat16*)(act + (45 + d * 10 + p) * 2) = __float2bfloat16(c);
                        float ns = 2.f * s * c;
                        float nc = fmaf(c, c, -(s * s));
                        s = ns; c = nc;
                    }
                }
            }
        }
        __syncthreads();

        // ---- layer 0: X(A) -> H1(B) ----
        gemm_layer<5>(ldA, ldW, acc);
        store_act(acc, sm + SM_ACTB, sBias, r0, c0, lane);
        __syncthreads();

        // ---- layer 1: H1(B) -> H2(A) ----
        gemm_layer<8>(ldB, ldW + 34816, acc);
        store_act(acc, sm + SM_ACTA, sBias + 128, r0, c0, lane);
        __syncthreads();

        // ---- layer 2: H2(A) -> H3(B) ----
        gemm_layer<8>(ldA, ldW + 2 * 34816, acc);
        store_act(acc, sm + SM_ACTB, sBias + 256, r0, c0, lane);
        __syncthreads();

        // ---- final: rgb = sigmoid([H3 | ve] @ Wr + br), write weight*rgb ----
        {
            const int row = tid >> 1, half = tid & 1;
            const int m = m0 + row;
            const uint32_t* hrow = (const uint32_t*)(sm + SM_ACTB + row * RSTRIDE) + half * 32;
            float d0 = 0.f, d1 = 0.f, d2 = 0.f;
#pragma unroll 8
            for (int k = 0; k < 32; k++) {
                float2 hv = __bfloat1622float2(*(const __nv_bfloat162*)&hrow[k]);
                int col = half * 64 + 2 * k;
                d0 = fmaf(hv.x, sWr[col * 3 + 0], fmaf(hv.y, sWr[(col + 1) * 3 + 0], d0));
                d1 = fmaf(hv.x, sWr[col * 3 + 1], fmaf(hv.y, sWr[(col + 1) * 3 + 1], d1));
                d2 = fmaf(hv.x, sWr[col * 3 + 2], fmaf(hv.y, sWr[(col + 1) * 3 + 2], d2));
            }
            d0 += __shfl_xor_sync(0xFFFFFFFFu, d0, 1);
            d1 += __shfl_xor_sync(0xFFFFFFFFu, d1, 1);
            d2 += __shfl_xor_sync(0xFFFFFFFFu, d2, 1);
            if (half == 0) {
                const int rid = __ldg(&ray_id[m]);
                const float wgt = g_weight[m];
                const float* vp = g_ve + rid * 27;
                float a0 = br0 + d0, a1 = br1 + d1, a2 = br2 + d2;
#pragma unroll
                for (int k = 0; k < 27; k++) {
                    float v = __ldg(&vp[k]);
                    a0 = fmaf(v, sWr[(128 + k) * 3 + 0], a0);
                    a1 = fmaf(v, sWr[(128 + k) * 3 + 1], a1);
                    a2 = fmaf(v, sWr[(128 + k) * 3 + 2], a2);
                }
                g_wrgb[3 * m + 0] = wgt * __fdividef(1.f, 1.f + __expf(-a0));
                g_wrgb[3 * m + 1] = wgt * __fdividef(1.f, 1.f + __expf(-a1));
                g_wrgb[3 * m + 2] = wgt * __fdividef(1.f, 1.f + __expf(-a2));
            }
        }
        // no tile-end barrier: next build writes ACTA only (see comment above)
    }
}

// ---------------- kernel 5: warp-per-ray reduction ----------------
__global__ void k_accum(const int* __restrict__ ray_id, float* __restrict__ out) {
    int r = blockIdx.x * 8 + (threadIdx.x >> 5);
    int lane = threadIdx.x & 31;
    if (r >= NRAYS) return;
    int s = lb_ray(ray_id, r);
    int e = lb_ray(ray_id, r + 1);
    float a0 = 0.f, a1 = 0.f, a2 = 0.f;
    for (int m = s + lane; m < e; m += 32) {
        a0 += g_wrgb[3 * m];
        a1 += g_wrgb[3 * m + 1];
        a2 += g_wrgb[3 * m + 2];
    }
#pragma unroll
    for (int off = 16; off > 0; off >>= 1) {
        a0 += __shfl_xor_sync(0xFFFFFFFFu, a0, off);
        a1 += __shfl_xor_sync(0xFFFFFFFFu, a1, off);
        a2 += __shfl_xor_sync(0xFFFFFFFFu, a2, off);
    }
    if (lane == 0) {
        out[3 * r]     += a0;
        out[3 * r + 1] += a1;
        out[3 * r + 2] += a2;
    }
}

// ---------------- launch ----------------
extern "C" void kernel_launch(void* const* d_in, const int* in_sizes, int n_in,
                              void* d_out, int out_size) {
    const float*         xyz      = (const float*)d_in[0];
    const int*           ray_id   = (const int*)d_in[1];
    const float*         viewdirs = (const float*)d_in[2];
    const unsigned char* mask     = (const unsigned char*)d_in[3];
    const float*         density  = (const float*)d_in[4];
    const float*         k0 = (const float*)d_in[5];
    const float*         W0 = (const float*)d_in[6];
    const float*         b0 = (const float*)d_in[7];
    const float*         W1 = (const float*)d_in[8];
    const float*         b1 = (const float*)d_in[9];
    const float*         W2 = (const float*)d_in[10];
    const float*         b2 = (const float*)d_in[11];
    const float*         Wr = (const float*)d_in[12];
    const float*         br = (const float*)d_in[13];
    float* out = (float*)d_out;

    static int smem_set = 0;
    if (!smem_set) {
        cudaFuncSetAttribute(k_mlp, cudaFuncAttributeMaxDynamicSharedMemorySize, DYN_SMEM);
        smem_set = 1;
    }

    k_wprep<<<(3 * 128 * 136 + 255) / 256, 256>>>(W0, W1, W2);
    k_ve<<<NRAYS / 256, 256>>>(viewdirs);
    k_alpha<<<MS / 256, 256>>>(xyz, mask, density);
    k_weights<<<NRAYS / 8, 256>>>(ray_id, out);
    k_mlp<<<148, 256, DYN_SMEM>>>(xyz, ray_id, k0, b0, b1, b2, Wr, br);
    k_accum<<<NRAYS / 8, 256>>>(ray_id, out);
}